// round 12
// baseline (speedup 1.0000x reference)
#include <cuda_runtime.h>
#include <cuda_fp16.h>
#include <math.h>
#include <math_constants.h>
#include <stdint.h>

#define B_    2
#define L_    2048
#define D_    2048
#define H_    16
#define KVH_  4
#define HD_   128
#define QKVD_ 3072          // packed q|k|v output row width
#define EPS_  1e-6f

typedef __half h16;

// ---------------------------------------------------------------------------
// Static scratch (all fp16)
// ---------------------------------------------------------------------------
__device__ h16 g_x16 [B_*L_*D_];
__device__ h16 g_wqkv[QKVD_*D_];        // rows 0-2047 Wq, 2048-2559 Wk, 2560-3071 Wv
__device__ h16 g_wo16[D_*D_];
__device__ h16 g_qkv [B_*L_*QKVD_];     // q cols 0-2047 (rms+roped), k cols 2048-2559
__device__ h16 g_vt  [B_*KVH_*HD_*L_];  // V transposed [b][kvh][d][L] (written by epilogue)
__device__ h16 g_ao  [B_*L_*D_];

// ---------------------------------------------------------------------------
// PTX helpers
// ---------------------------------------------------------------------------
__device__ __forceinline__ void mma_f16(float* c, const uint32_t* a, const uint32_t* b) {
    asm volatile(
        "mma.sync.aligned.m16n8k16.row.col.f32.f16.f16.f32 "
        "{%0,%1,%2,%3}, {%4,%5,%6,%7}, {%8,%9}, {%0,%1,%2,%3};\n"
        : "+f"(c[0]), "+f"(c[1]), "+f"(c[2]), "+f"(c[3])
        : "r"(a[0]), "r"(a[1]), "r"(a[2]), "r"(a[3]), "r"(b[0]), "r"(b[1]));
}

__device__ __forceinline__ void cp16(const h16* dst_s, const h16* src_g) {
    uint32_t d = (uint32_t)__cvta_generic_to_shared(dst_s);
    asm volatile("cp.async.cg.shared.global [%0], [%1], 16;\n"
                 :: "r"(d), "l"(src_g) : "memory");
}
__device__ __forceinline__ void cp_commit() {
    asm volatile("cp.async.commit_group;\n" ::: "memory");
}
template<int N>
__device__ __forceinline__ void cp_wait() {
    asm volatile("cp.async.wait_group %0;\n" :: "n"(N) : "memory");
}

// pack two fp32 -> fp16x2 (lo = first arg, hi = second)
__device__ __forceinline__ uint32_t cvt2(float lo, float hi) {
    uint32_t r;
    asm("cvt.rn.f16x2.f32 %0, %1, %2;" : "=r"(r) : "f"(hi), "f"(lo));
    return r;
}

// ---------------------------------------------------------------------------
// GEMM: C[M,N] = A[M,K](h16) * B[N,K]^T(h16), fp32 acc.
// MODE 0: fp32 out (O projection).
// MODE 3: merged QKV projection epilogue:
//   n0 < 2048          -> fp16 out + rmsnorm+rope (qgamma)
//   2048 <= n0 < 2560  -> fp16 out + rmsnorm+rope (kgamma)
//   n0 >= 2560         -> V: transposed fp16 store into vt[b][kvh][d][L]
// ---------------------------------------------------------------------------
#define BM 128
#define BN 128
#define BK 32
#define APAD 40

#define SM_A_HALVES (2*BM*APAD)
#define SM_B_HALVES (2*BN*APAD)
#define SMEM_TB_BYTES ((SM_A_HALVES + SM_B_HALVES)*2)   // 40960

#define INVF_C 0.2076205059304601f    // log2(10000)/64

template<int MODE>
__global__ __launch_bounds__(256, 2)
void k_gemm(const h16* __restrict__ A, int lda,
            const h16* __restrict__ Bh, int ldb,
            void* __restrict__ Cv, int ldc, int K,
            const float* __restrict__ qgamma,
            const float* __restrict__ kgamma,
            h16* __restrict__ vt)
{
    extern __shared__ h16 sh[];
    h16* sA = sh;
    h16* sB = sh + SM_A_HALVES;

    const int tid = threadIdx.x;
    const int m0 = blockIdx.y * BM;
    const int n0 = blockIdx.x * BN;

    const h16* Ap = A  + (size_t)m0 * lda;
    const h16* Bp = Bh + (size_t)n0 * ldb;

    const int lane = tid & 31;
    const int g    = lane >> 2;
    const int t    = lane & 3;
    const int warp = tid >> 5;
    const int wm   = warp >> 2;
    const int wn   = warp & 3;

    float acc[4][4][4];
#pragma unroll
    for (int i = 0; i < 4; i++)
#pragma unroll
        for (int j = 0; j < 4; j++)
#pragma unroll
            for (int c = 0; c < 4; c++) acc[i][j][c] = 0.f;

    auto load_stage = [&](int s, int k0) {
#pragma unroll
        for (int i = 0; i < 2; i++) {
            int c   = tid + i * 256;
            int row = c >> 2, kc = c & 3;
            cp16(sA + (size_t)s*BM*APAD + row*APAD + kc*8,
                 Ap + (size_t)row * lda + k0 + kc*8);
        }
#pragma unroll
        for (int i = 0; i < 2; i++) {
            int c   = tid + i * 256;
            int row = c >> 2, kc = c & 3;
            cp16(sB + (size_t)s*BN*APAD + row*APAD + kc*8,
                 Bp + (size_t)row * ldb + k0 + kc*8);
        }
    };

    const int nk = K / BK;
    load_stage(0, 0);
    cp_commit();

    for (int ks = 0; ks < nk; ks++) {
        const int buf = ks & 1;
        if (ks + 1 < nk) {
            load_stage(buf ^ 1, (ks + 1) * BK);
            cp_commit();
            cp_wait<1>();
        } else {
            cp_wait<0>();
        }
        __syncthreads();

        const h16* sAb = sA + (size_t)buf*BM*APAD;
        const h16* sBb = sB + (size_t)buf*BN*APAD;

#pragma unroll
        for (int kk = 0; kk < 2; kk++) {
            const int ko = kk * 16;

            uint32_t ah[4][4];
#pragma unroll
            for (int mt = 0; mt < 4; mt++) {
                const int r = wm*64 + mt*16 + g;
                const h16* p0 = sAb + r*APAD + ko + 2*t;
                ah[mt][0] = *(const uint32_t*)(p0);
                ah[mt][1] = *(const uint32_t*)(p0 + 8*APAD);
                ah[mt][2] = *(const uint32_t*)(p0 + 8);
                ah[mt][3] = *(const uint32_t*)(p0 + 8*APAD + 8);
            }

            uint32_t bh[4][2];
#pragma unroll
            for (int nt = 0; nt < 4; nt++) {
                const int n = wn*32 + nt*8 + g;
                const h16* p0 = sBb + n*APAD + ko + 2*t;
                bh[nt][0] = *(const uint32_t*)(p0);
                bh[nt][1] = *(const uint32_t*)(p0 + 8);
            }

#pragma unroll
            for (int mt = 0; mt < 4; mt++)
#pragma unroll
                for (int nt = 0; nt < 4; nt++)
                    mma_f16(acc[mt][nt], ah[mt], bh[nt]);
        }
        __syncthreads();
    }

    // ---------------- epilogue ----------------
    if constexpr (MODE == 0) {
        float* C = (float*)Cv;
#pragma unroll
        for (int mt = 0; mt < 4; mt++) {
            const int r = m0 + wm*64 + mt*16 + g;
#pragma unroll
            for (int nt = 0; nt < 4; nt++) {
                const int c = n0 + wn*32 + nt*8 + 2*t;
                *reinterpret_cast<float2*>(&C[(size_t)r     * ldc + c]) =
                    make_float2(acc[mt][nt][0], acc[mt][nt][1]);
                *reinterpret_cast<float2*>(&C[(size_t)(r+8) * ldc + c]) =
                    make_float2(acc[mt][nt][2], acc[mt][nt][3]);
            }
        }
    } else {
        h16* C = (h16*)Cv;
        if (n0 >= 2560) {
            // ---- V: store transposed into vt[b][kvh][d][L] ----
            const int kvh = (n0 - 2560) >> 7;
#pragma unroll
            for (int mt = 0; mt < 4; mt++)
#pragma unroll
                for (int hh = 0; hh < 2; hh++) {
                    const int r  = m0 + wm*64 + mt*16 + g + hh*8;
                    const int bb = r >> 11;
                    const int ll = r & (L_ - 1);
#pragma unroll
                    for (int nt = 0; nt < 4; nt++) {
                        const int d = wn*32 + nt*8 + 2*t;
                        size_t base = ((size_t)(bb*KVH_ + kvh)*HD_ + d)*L_ + ll;
                        vt[base]      = __float2half_rn(acc[mt][nt][2*hh]);
                        vt[base + L_] = __float2half_rn(acc[mt][nt][2*hh+1]);
                    }
                }
        } else {
            // ---- Q or K: fused rmsnorm + rope (block = exactly one head) ----
            const float* gamma = (n0 < 2048) ? qgamma : kgamma;
            float* red = (float*)sh;
            float part[4][2];
#pragma unroll
            for (int mt = 0; mt < 4; mt++)
#pragma unroll
                for (int hh = 0; hh < 2; hh++) {
                    float p = 0.f;
#pragma unroll
                    for (int nt = 0; nt < 4; nt++) {
                        float a0 = acc[mt][nt][2*hh], a1 = acc[mt][nt][2*hh+1];
                        p += a0*a0 + a1*a1;
                    }
                    p += __shfl_xor_sync(0xffffffffu, p, 1);
                    p += __shfl_xor_sync(0xffffffffu, p, 2);
                    part[mt][hh] = p;
                }
            if (t == 0) {
#pragma unroll
                for (int mt = 0; mt < 4; mt++)
#pragma unroll
                    for (int hh = 0; hh < 2; hh++)
                        red[(wm*64 + mt*16 + g + hh*8)*4 + wn] = part[mt][hh];
            }
            __syncthreads();

            float invv[4][2];
#pragma unroll
            for (int mt = 0; mt < 4; mt++)
#pragma unroll
                for (int hh = 0; hh < 2; hh++) {
                    int rl = wm*64 + mt*16 + g + hh*8;
                    float s = red[rl*4] + red[rl*4+1] + red[rl*4+2] + red[rl*4+3];
                    invv[mt][hh] = rsqrtf(s * (1.0f/HD_) + EPS_);
                }

            float invf[4], g0[4], g1[4];
#pragma unroll
            for (int nt = 0; nt < 4; nt++) {
                int p = wn*16 + nt*4 + t;
                invf[nt] = exp2f(-(float)p * INVF_C);
                g0[nt] = gamma[2*p];
                g1[nt] = gamma[2*p+1];
            }

#pragma unroll
            for (int mt = 0; mt < 4; mt++)
#pragma unroll
                for (int hh = 0; hh < 2; hh++) {
                    const int r  = m0 + wm*64 + mt*16 + g + hh*8;
                    const float fl = (float)(r & (L_-1));
                    const float iv = invv[mt][hh];
#pragma unroll
                    for (int nt = 0; nt < 4; nt++) {
                        float sn, cs;
                        sincosf(fl * invf[nt], &sn, &cs);
                        float re = acc[mt][nt][2*hh]   * iv * g0[nt];
                        float im = acc[mt][nt][2*hh+1] * iv * g1[nt];
                        h16* dst = C + (size_t)r * ldc + n0 + wn*32 + nt*8 + 2*t;
                        *(uint32_t*)dst = cvt2(re*cs - im*sn, re*sn + im*cs);
                    }
                }
        }
    }
}

// ---------------------------------------------------------------------------
// fp32->fp16 conversion: x + packed Wq|Wk|Wv; Wo separately (stream s2)
// ---------------------------------------------------------------------------
#define CS0 2097152u                 // x (f4 units)
#define CS1 (CS0 + 1048576u)         // + Wq
#define CS2 (CS1 + 262144u)          // + Wk
#define CS3 (CS2 + 262144u)          // + Wv -> 3670016

__device__ __forceinline__ ushort4 cvt4(float4 v) {
    uint32_t lo = 0, hi = 0;
    asm("cvt.rn.f16x2.f32 %0, %1, %2;" : "=r"(lo) : "f"(v.y), "f"(v.x));
    asm("cvt.rn.f16x2.f32 %0, %1, %2;" : "=r"(hi) : "f"(v.w), "f"(v.z));
    ushort4 r;
    r.x = (unsigned short)(lo & 0xffff);
    r.y = (unsigned short)(lo >> 16);
    r.z = (unsigned short)(hi & 0xffff);
    r.w = (unsigned short)(hi >> 16);
    return r;
}

__global__ void k_cvt_main(const float4* __restrict__ x, const float4* __restrict__ wq,
                           const float4* __restrict__ wk, const float4* __restrict__ wv)
{
    uint32_t i = blockIdx.x * 256u + threadIdx.x;
    ushort4* xh = (ushort4*)g_x16;
    ushort4* wh = (ushort4*)g_wqkv;
    if (i < CS0)      xh[i]                  = cvt4(x [i]);
    else if (i < CS1) wh[i - CS0]            = cvt4(wq[i - CS0]);
    else if (i < CS2) wh[i - CS1 + 1048576u] = cvt4(wk[i - CS1]);
    else if (i < CS3) wh[i - CS2 + 1310720u] = cvt4(wv[i - CS2]);
}

__global__ void k_cvt_wo(const float4* __restrict__ wo)
{
    uint32_t i = blockIdx.x * 256u + threadIdx.x;
    ((ushort4*)g_wo16)[i] = cvt4(wo[i]);
}

// ---------------------------------------------------------------------------
// Fused flash attention, fixed-shift softmax, tiles order-independent.
// 128 threads (4 warps), q-tile 64, occupancy 2. Q/K read from packed QKV.
// ---------------------------------------------------------------------------
#define QPAD 136
#define VPAD 72

#define QPL  (64*QPAD)
#define KPL  (64*QPAD)
#define VPL  (128*VPAD)
#define QS_OFF 0
#define KS_OFF QPL
#define VS_OFF (KS_OFF + 2*KPL)
#define MS_OFF_H (VS_OFF + 2*VPL)
#define FA_SMEM_BYTES (MS_OFF_H*2 + 2*64*4)   // 89600

__global__ __launch_bounds__(128, 2)
void k_flash(const h16* __restrict__ qkv,
             const h16* __restrict__ vt,
             const int* __restrict__ mask,
             h16* __restrict__ ao)
{
    extern __shared__ h16 sm[];
    h16*   Qs = sm + QS_OFF;
    h16*   Ks = sm + KS_OFF;
    h16*   Vs = sm + VS_OFF;
    float* Ms = (float*)(sm + MS_OFF_H);

    const int tid  = threadIdx.x;
    const int lane = tid & 31;
    const int g    = lane >> 2;
    const int t    = lane & 3;
    const int w    = tid >> 5;

    const int qt = blockIdx.x, h = blockIdx.y, b = blockIdx.z;
    const int kvh = h >> 2;
    const int q0  = qt * 64;

    const h16* Qg = qkv + ((size_t)(b*L_ + q0)) * QKVD_ + h * HD_;
    const h16* Kg = qkv + ((size_t)(b*L_)) * QKVD_ + 2048 + kvh * HD_;
    const h16* Vg = vt + ((size_t)(b*KVH_ + kvh)) * HD_ * L_;

#pragma unroll
    for (int i = 0; i < 8; i++) {
        int c = tid + i * 128;
        int row = c >> 4, ch = c & 15;
        cp16(Qs + row*QPAD + ch*8, Qg + (size_t)row * QKVD_ + ch*8);
    }

    auto load_stage = [&](int s, int kt) {
        const int j0 = kt * 64;
#pragma unroll
        for (int i = 0; i < 8; i++) {
            int c = tid + i * 128;
            int row = c >> 4, ch = c & 15;
            cp16(Ks + s*KPL + row*QPAD + ch*8,
                 Kg + (size_t)(j0 + row) * QKVD_ + ch*8);
        }
#pragma unroll
        for (int i = 0; i < 8; i++) {
            int c = tid + i * 128;
            int row = c >> 3, ch = c & 7;
            cp16(Vs + s*VPL + row*VPAD + ch*8,
                 Vg + (size_t)row * L_ + j0 + ch*8);
        }
        if (tid < 64)
            Ms[s*64 + tid] = mask[b*L_ + j0 + tid] ? -6.0f : -1e30f;
    };

    load_stage(0, 0);
    cp_commit();

    float o[16][4];
#pragma unroll
    for (int i = 0; i < 16; i++)
#pragma unroll
        for (int c = 0; c < 4; c++) o[i][c] = 0.f;

    float lsum0 = 0.f, lsum1 = 0.f;
    const float sc = 0.08838834764831845f;

    const int NT_ = L_ / 64;
    for (int kt = 0; kt < NT_; kt++) {
        const int buf = kt & 1;
        if (kt + 1 < NT_) {
            load_stage(buf ^ 1, kt + 1);
            cp_commit();
            cp_wait<1>();
        } else {
            cp_wait<0>();
        }
        __syncthreads();

        float s[8][4];
#pragma unroll
        for (int nt = 0; nt < 8; nt++)
#pragma unroll
            for (int c = 0; c < 4; c++) s[nt][c] = 0.f;

        const h16* qb = Qs + (w*16 + g)*QPAD + 2*t;
        const h16* kb = Ks + buf*KPL + g*QPAD + 2*t;

#pragma unroll
        for (int kk = 0; kk < 8; kk++) {
            const int ko = kk * 16;
            uint32_t ah[4];
            ah[0] = *(const uint32_t*)(qb + ko);
            ah[1] = *(const uint32_t*)(qb + ko + 8*QPAD);
            ah[2] = *(const uint32_t*)(qb + ko + 8);
            ah[3] = *(const uint32_t*)(qb + ko + 8*QPAD + 8);
#pragma unroll
            for (int nt = 0; nt < 8; nt++) {
                uint32_t bh[2];
                const h16* pk = kb + nt*8*QPAD + ko;
                bh[0] = *(const uint32_t*)(pk);
                bh[1] = *(const uint32_t*)(pk + 8);
                mma_f16(s[nt], ah, bh);
            }
        }

        const float* msf = Ms + buf*64;
        uint32_t pah[4][4];
#pragma unroll
        for (int kk = 0; kk < 4; kk++) {
            const int n0t = 2*kk, n1t = 2*kk + 1;
            float b00 = msf[8*n0t + 2*t], b01 = msf[8*n0t + 2*t + 1];
            float b10 = msf[8*n1t + 2*t], b11 = msf[8*n1t + 2*t + 1];
            float p00 = __expf(s[n0t][0]*sc + b00);
            float p01 = __expf(s[n0t][1]*sc + b01);
            float p02 = __expf(s[n0t][2]*sc + b00);
            float p03 = __expf(s[n0t][3]*sc + b01);
            float p10 = __expf(s[n1t][0]*sc + b10);
            float p11 = __expf(s[n1t][1]*sc + b11);
            float p12 = __expf(s[n1t][2]*sc + b10);
            float p13 = __expf(s[n1t][3]*sc + b11);
            lsum0 += p00 + p01 + p10 + p11;
            lsum1 += p02 + p03 + p12 + p13;
            pah[kk][0] = cvt2(p00, p01);
            pah[kk][1] = cvt2(p02, p03);
            pah[kk][2] = cvt2(p10, p11);
            pah[kk][3] = cvt2(p12, p13);
        }

        const h16* vb = Vs + buf*VPL + g*VPAD + 2*t;
#pragma unroll
        for (int kk = 0; kk < 4; kk++) {
            const int ko = kk * 16;
#pragma unroll
            for (int nt = 0; nt < 16; nt++) {
                uint32_t bh[2];
                const h16* pv = vb + nt*8*VPAD + ko;
                bh[0] = *(const uint32_t*)(pv);
                bh[1] = *(const uint32_t*)(pv + 8);
                mma_f16(o[nt], pah[kk], bh);
            }
        }
        __syncthreads();
    }

    lsum0 += __shfl_xor_sync(0xffffffffu, lsum0, 1);
    lsum0 += __shfl_xor_sync(0xffffffffu, lsum0, 2);
    lsum1 += __shfl_xor_sync(0xffffffffu, lsum1, 1);
    lsum1 += __shfl_xor_sync(0xffffffffu, lsum1, 2);

    const float inv0 = lsum0 > 0.f ? 1.f / lsum0 : 0.f;
    const float inv1 = lsum1 > 0.f ? 1.f / lsum1 : 0.f;
    const int row0 = q0 + w*16 + g;
    const size_t base0 = (size_t)(b*L_ + row0) * D_ + h * HD_;
    const size_t base1 = base0 + 8 * (size_t)D_;

#pragma unroll
    for (int nt = 0; nt < 16; nt++) {
        const int col = nt*8 + 2*t;
        *(uint32_t*)(ao + base0 + col) = cvt2(o[nt][0] * inv0, o[nt][1] * inv0);
        *(uint32_t*)(ao + base1 + col) = cvt2(o[nt][2] * inv1, o[nt][3] * inv1);
    }
}

// ---------------------------------------------------------------------------
// Launch
// ---------------------------------------------------------------------------
extern "C" void kernel_launch(void* const* d_in, const int* in_sizes, int n_in,
                              void* d_out, int out_size) {
    const float* x    = (const float*)d_in[0];
    const int*   mask = (const int*)  d_in[1];
    const float* Wq   = (const float*)d_in[2];
    const float* Wk   = (const float*)d_in[3];
    const float* Wv   = (const float*)d_in[4];
    const float* Wo   = (const float*)d_in[5];
    const float* qg   = (const float*)d_in[6];
    const float* kg   = (const float*)d_in[7];
    float* out = (float*)d_out;

    h16 *x16, *wqkv, *wo16, *qkvp, *vtp, *aop;
    cudaGetSymbolAddress((void**)&x16,  g_x16);
    cudaGetSymbolAddress((void**)&wqkv, g_wqkv);
    cudaGetSymbolAddress((void**)&wo16, g_wo16);
    cudaGetSymbolAddress((void**)&qkvp, g_qkv);
    cudaGetSymbolAddress((void**)&vtp,  g_vt);
    cudaGetSymbolAddress((void**)&aop,  g_ao);

    cudaFuncSetAttribute(k_flash, cudaFuncAttributeMaxDynamicSharedMemorySize,
                         FA_SMEM_BYTES);

    static cudaStream_t s2 = nullptr;
    static cudaEvent_t e0 = nullptr, e2 = nullptr;
    if (!s2) {
        cudaStreamCreateWithFlags(&s2, cudaStreamNonBlocking);
        cudaEventCreateWithFlags(&e0, cudaEventDisableTiming);
        cudaEventCreateWithFlags(&e2, cudaEventDisableTiming);
    }

    const int M = B_ * L_;
    dim3 blk(256);

    // fork: Wo conversion runs concurrently until O-proj
    cudaEventRecord(e0, 0);
    cudaStreamWaitEvent(s2, e0, 0);
    k_cvt_wo<<<1048576u/256u, 256, 0, s2>>>((const float4*)Wo);
    cudaEventRecord(e2, s2);

    // x + packed Wq|Wk|Wv conversion
    k_cvt_main<<<CS3/256u, 256>>>((const float4*)x, (const float4*)Wq,
                                  (const float4*)Wk, (const float4*)Wv);

    // merged QKV projection (Q/K rms+rope fused; V written transposed)
    k_gemm<3><<<dim3(QKVD_/BN, M/BM), blk, SMEM_TB_BYTES>>>(
        x16, D_, wqkv, D_, qkvp, QKVD_, D_, qg, kg, vtp);

    // fused flash attention
    k_flash<<<dim3(L_/64, H_, B_), 128, FA_SMEM_BYTES>>>(qkvp, vtp, mask, aop);

    // join s2, output projection (fp32 out)
    cudaStreamWaitEvent(0, e2, 0);
    k_gemm<0><<<dim3(D_/BN, M/BM), blk, SMEM_TB_BYTES>>>(
        aop, D_, wo16, D_, out, D_, D_, nullptr, nullptr, nullptr);
}

// round 13
// speedup vs baseline: 1.0481x; 1.0481x over previous
#include <cuda_runtime.h>
#include <cuda_fp16.h>
#include <math.h>
#include <math_constants.h>
#include <stdint.h>

#define B_    2
#define L_    2048
#define D_    2048
#define H_    16
#define KVH_  4
#define HD_   128
#define QKVD_ 3072
#define EPS_  1e-6f

typedef __half h16;

// ---------------------------------------------------------------------------
// Static scratch (all fp16)
// ---------------------------------------------------------------------------
__device__ h16 g_x16 [B_*L_*D_];
__device__ h16 g_wqkv[QKVD_*D_];        // rows 0-2047 Wq, 2048-2559 Wk, 2560-3071 Wv
__device__ h16 g_wo16[D_*D_];
__device__ h16 g_qkv [B_*L_*QKVD_];
__device__ h16 g_vt  [B_*KVH_*HD_*L_];
__device__ h16 g_ao  [B_*L_*D_];

// ---------------------------------------------------------------------------
// PTX helpers
// ---------------------------------------------------------------------------
__device__ __forceinline__ void mma_f16(float* c, const uint32_t* a, const uint32_t* b) {
    asm volatile(
        "mma.sync.aligned.m16n8k16.row.col.f32.f16.f16.f32 "
        "{%0,%1,%2,%3}, {%4,%5,%6,%7}, {%8,%9}, {%0,%1,%2,%3};\n"
        : "+f"(c[0]), "+f"(c[1]), "+f"(c[2]), "+f"(c[3])
        : "r"(a[0]), "r"(a[1]), "r"(a[2]), "r"(a[3]), "r"(b[0]), "r"(b[1]));
}

// ldmatrix x4: 4 8x8 b16 matrices; lanes 8i..8i+7 address matrix i's rows.
__device__ __forceinline__ void ldsm4(uint32_t* r, uint32_t saddr) {
    asm volatile("ldmatrix.sync.aligned.m8n8.x4.shared.b16 {%0,%1,%2,%3}, [%4];"
        : "=r"(r[0]), "=r"(r[1]), "=r"(r[2]), "=r"(r[3]) : "r"(saddr));
}

__device__ __forceinline__ void cp16(const h16* dst_s, const h16* src_g) {
    uint32_t d = (uint32_t)__cvta_generic_to_shared(dst_s);
    asm volatile("cp.async.cg.shared.global [%0], [%1], 16;\n"
                 :: "r"(d), "l"(src_g) : "memory");
}
__device__ __forceinline__ void cp_commit() {
    asm volatile("cp.async.commit_group;\n" ::: "memory");
}
template<int N>
__device__ __forceinline__ void cp_wait() {
    asm volatile("cp.async.wait_group %0;\n" :: "n"(N) : "memory");
}

__device__ __forceinline__ uint32_t cvt2(float lo, float hi) {
    uint32_t r;
    asm("cvt.rn.f16x2.f32 %0, %1, %2;" : "=r"(r) : "f"(hi), "f"(lo));
    return r;
}

// ---------------------------------------------------------------------------
// GEMM: C[M,N] = A[M,K](h16) * B[N,K]^T(h16), fp32 acc. ldmatrix fragment loads.
// MODE 0: fp32 out (O projection).
// MODE 3: merged QKV epilogue (Q/K rms+rope; V transposed store).
// ---------------------------------------------------------------------------
#define BM 128
#define BN 128
#define BK 32
#define APAD 40

#define SM_A_HALVES (2*BM*APAD)
#define SM_B_HALVES (2*BN*APAD)
#define SMEM_TB_BYTES ((SM_A_HALVES + SM_B_HALVES)*2)   // 40960

#define INVF_C 0.2076205059304601f    // log2(10000)/64

template<int MODE>
__global__ __launch_bounds__(256, 2)
void k_gemm(const h16* __restrict__ A, int lda,
            const h16* __restrict__ Bh, int ldb,
            void* __restrict__ Cv, int ldc, int K,
            const float* __restrict__ qgamma,
            const float* __restrict__ kgamma,
            h16* __restrict__ vt)
{
    extern __shared__ h16 sh[];
    h16* sA = sh;
    h16* sB = sh + SM_A_HALVES;

    const int tid = threadIdx.x;
    const int m0 = blockIdx.y * BM;
    const int n0 = blockIdx.x * BN;

    const h16* Ap = A  + (size_t)m0 * lda;
    const h16* Bp = Bh + (size_t)n0 * ldb;

    const int lane = tid & 31;
    const int g    = lane >> 2;
    const int t    = lane & 3;
    const int warp = tid >> 5;
    const int wm   = warp >> 2;
    const int wn   = warp & 3;

    // ldmatrix per-lane address components
    const int a_row = (lane & 7) + ((lane >> 3) & 1) * 8;   // within 16-row fragment
    const int a_c8  = ((lane >> 4) & 1) * 8;                // +8 cols for mats 2,3
    const int b_row = (lane & 7) + ((lane >> 4) & 1) * 8;   // +8 rows for mats 2,3
    const int b_c8  = ((lane >> 3) & 1) * 8;                // +8 cols for mats 1,3

    const uint32_t sAu = (uint32_t)__cvta_generic_to_shared(sA);
    const uint32_t sBu = (uint32_t)__cvta_generic_to_shared(sB);

    float acc[4][4][4];
#pragma unroll
    for (int i = 0; i < 4; i++)
#pragma unroll
        for (int j = 0; j < 4; j++)
#pragma unroll
            for (int c = 0; c < 4; c++) acc[i][j][c] = 0.f;

    auto load_stage = [&](int s, int k0) {
#pragma unroll
        for (int i = 0; i < 2; i++) {
            int c   = tid + i * 256;
            int row = c >> 2, kc = c & 3;
            cp16(sA + (size_t)s*BM*APAD + row*APAD + kc*8,
                 Ap + (size_t)row * lda + k0 + kc*8);
        }
#pragma unroll
        for (int i = 0; i < 2; i++) {
            int c   = tid + i * 256;
            int row = c >> 2, kc = c & 3;
            cp16(sB + (size_t)s*BN*APAD + row*APAD + kc*8,
                 Bp + (size_t)row * ldb + k0 + kc*8);
        }
    };

    const int nk = K / BK;
    load_stage(0, 0);
    cp_commit();

    for (int ks = 0; ks < nk; ks++) {
        const int buf = ks & 1;
        if (ks + 1 < nk) {
            load_stage(buf ^ 1, (ks + 1) * BK);
            cp_commit();
            cp_wait<1>();
        } else {
            cp_wait<0>();
        }
        __syncthreads();

        const uint32_t aBase = sAu + (uint32_t)(buf*BM*APAD + (wm*64 + a_row)*APAD + a_c8) * 2u;
        const uint32_t bBase = sBu + (uint32_t)(buf*BN*APAD + (wn*32 + b_row)*APAD + b_c8) * 2u;

#pragma unroll
        for (int kk = 0; kk < 2; kk++) {
            const int ko = kk * 16;

            uint32_t ah[4][4];
#pragma unroll
            for (int mt = 0; mt < 4; mt++)
                ldsm4(ah[mt], aBase + (uint32_t)(mt*16*APAD + ko) * 2u);

            uint32_t bb[2][4];
#pragma unroll
            for (int nt2 = 0; nt2 < 2; nt2++)
                ldsm4(bb[nt2], bBase + (uint32_t)(nt2*16*APAD + ko) * 2u);

#pragma unroll
            for (int mt = 0; mt < 4; mt++)
#pragma unroll
                for (int nt2 = 0; nt2 < 2; nt2++) {
                    mma_f16(acc[mt][2*nt2],   ah[mt], bb[nt2]);
                    mma_f16(acc[mt][2*nt2+1], ah[mt], bb[nt2] + 2);
                }
        }
        __syncthreads();
    }

    // ---------------- epilogue ----------------
    if constexpr (MODE == 0) {
        float* C = (float*)Cv;
#pragma unroll
        for (int mt = 0; mt < 4; mt++) {
            const int r = m0 + wm*64 + mt*16 + g;
#pragma unroll
            for (int nt = 0; nt < 4; nt++) {
                const int c = n0 + wn*32 + nt*8 + 2*t;
                *reinterpret_cast<float2*>(&C[(size_t)r     * ldc + c]) =
                    make_float2(acc[mt][nt][0], acc[mt][nt][1]);
                *reinterpret_cast<float2*>(&C[(size_t)(r+8) * ldc + c]) =
                    make_float2(acc[mt][nt][2], acc[mt][nt][3]);
            }
        }
    } else {
        h16* C = (h16*)Cv;
        if (n0 >= 2560) {
            const int kvh = (n0 - 2560) >> 7;
#pragma unroll
            for (int mt = 0; mt < 4; mt++)
#pragma unroll
                for (int hh = 0; hh < 2; hh++) {
                    const int r  = m0 + wm*64 + mt*16 + g + hh*8;
                    const int bb2 = r >> 11;
                    const int ll = r & (L_ - 1);
#pragma unroll
                    for (int nt = 0; nt < 4; nt++) {
                        const int d = wn*32 + nt*8 + 2*t;
                        size_t base = ((size_t)(bb2*KVH_ + kvh)*HD_ + d)*L_ + ll;
                        vt[base]      = __float2half_rn(acc[mt][nt][2*hh]);
                        vt[base + L_] = __float2half_rn(acc[mt][nt][2*hh+1]);
                    }
                }
        } else {
            const float* gamma = (n0 < 2048) ? qgamma : kgamma;
            float* red = (float*)sh;
            float part[4][2];
#pragma unroll
            for (int mt = 0; mt < 4; mt++)
#pragma unroll
                for (int hh = 0; hh < 2; hh++) {
                    float p = 0.f;
#pragma unroll
                    for (int nt = 0; nt < 4; nt++) {
                        float a0 = acc[mt][nt][2*hh], a1 = acc[mt][nt][2*hh+1];
                        p += a0*a0 + a1*a1;
                    }
                    p += __shfl_xor_sync(0xffffffffu, p, 1);
                    p += __shfl_xor_sync(0xffffffffu, p, 2);
                    part[mt][hh] = p;
                }
            if (t == 0) {
#pragma unroll
                for (int mt = 0; mt < 4; mt++)
#pragma unroll
                    for (int hh = 0; hh < 2; hh++)
                        red[(wm*64 + mt*16 + g + hh*8)*4 + wn] = part[mt][hh];
            }
            __syncthreads();

            float invv[4][2];
#pragma unroll
            for (int mt = 0; mt < 4; mt++)
#pragma unroll
                for (int hh = 0; hh < 2; hh++) {
                    int rl = wm*64 + mt*16 + g + hh*8;
                    float s = red[rl*4] + red[rl*4+1] + red[rl*4+2] + red[rl*4+3];
                    invv[mt][hh] = rsqrtf(s * (1.0f/HD_) + EPS_);
                }

            float invf[4], g0[4], g1[4];
#pragma unroll
            for (int nt = 0; nt < 4; nt++) {
                int p = wn*16 + nt*4 + t;
                invf[nt] = exp2f(-(float)p * INVF_C);
                g0[nt] = gamma[2*p];
                g1[nt] = gamma[2*p+1];
            }

#pragma unroll
            for (int mt = 0; mt < 4; mt++)
#pragma unroll
                for (int hh = 0; hh < 2; hh++) {
                    const int r  = m0 + wm*64 + mt*16 + g + hh*8;
                    const float fl = (float)(r & (L_-1));
                    const float iv = invv[mt][hh];
#pragma unroll
                    for (int nt = 0; nt < 4; nt++) {
                        float sn, cs;
                        sincosf(fl * invf[nt], &sn, &cs);
                        float re = acc[mt][nt][2*hh]   * iv * g0[nt];
                        float im = acc[mt][nt][2*hh+1] * iv * g1[nt];
                        h16* dst = C + (size_t)r * ldc + n0 + wn*32 + nt*8 + 2*t;
                        *(uint32_t*)dst = cvt2(re*cs - im*sn, re*sn + im*cs);
                    }
                }
        }
    }
}

// ---------------------------------------------------------------------------
// fp32->fp16 conversion
// ---------------------------------------------------------------------------
#define CS0 2097152u
#define CS1 (CS0 + 1048576u)
#define CS2 (CS1 + 262144u)
#define CS3 (CS2 + 262144u)

__device__ __forceinline__ ushort4 cvt4(float4 v) {
    uint32_t lo = 0, hi = 0;
    asm("cvt.rn.f16x2.f32 %0, %1, %2;" : "=r"(lo) : "f"(v.y), "f"(v.x));
    asm("cvt.rn.f16x2.f32 %0, %1, %2;" : "=r"(hi) : "f"(v.w), "f"(v.z));
    ushort4 r;
    r.x = (unsigned short)(lo & 0xffff);
    r.y = (unsigned short)(lo >> 16);
    r.z = (unsigned short)(hi & 0xffff);
    r.w = (unsigned short)(hi >> 16);
    return r;
}

__global__ void k_cvt_main(const float4* __restrict__ x, const float4* __restrict__ wq,
                           const float4* __restrict__ wk, const float4* __restrict__ wv)
{
    uint32_t i = blockIdx.x * 256u + threadIdx.x;
    ushort4* xh = (ushort4*)g_x16;
    ushort4* wh = (ushort4*)g_wqkv;
    if (i < CS0)      xh[i]                  = cvt4(x [i]);
    else if (i < CS1) wh[i - CS0]            = cvt4(wq[i - CS0]);
    else if (i < CS2) wh[i - CS1 + 1048576u] = cvt4(wk[i - CS1]);
    else if (i < CS3) wh[i - CS2 + 1310720u] = cvt4(wv[i - CS2]);
}

__global__ void k_cvt_wo(const float4* __restrict__ wo)
{
    uint32_t i = blockIdx.x * 256u + threadIdx.x;
    ((ushort4*)g_wo16)[i] = cvt4(wo[i]);
}

// ---------------------------------------------------------------------------
// Fused flash attention, fixed-shift softmax, ldmatrix fragment loads.
// 128 threads (4 warps), q-tile 64, occupancy 2.
// ---------------------------------------------------------------------------
#define QPAD 136
#define VPAD 72

#define QPL  (64*QPAD)
#define KPL  (64*QPAD)
#define VPL  (128*VPAD)
#define QS_OFF 0
#define KS_OFF QPL
#define VS_OFF (KS_OFF + 2*KPL)
#define MS_OFF_H (VS_OFF + 2*VPL)
#define FA_SMEM_BYTES (MS_OFF_H*2 + 2*64*4)   // 89600

__global__ __launch_bounds__(128, 2)
void k_flash(const h16* __restrict__ qkv,
             const h16* __restrict__ vt,
             const int* __restrict__ mask,
             h16* __restrict__ ao)
{
    extern __shared__ h16 sm[];
    h16*   Qs = sm + QS_OFF;
    h16*   Ks = sm + KS_OFF;
    h16*   Vs = sm + VS_OFF;
    float* Ms = (float*)(sm + MS_OFF_H);

    const int tid  = threadIdx.x;
    const int lane = tid & 31;
    const int t    = lane & 3;
    const int w    = tid >> 5;

    const int qt = blockIdx.x, h = blockIdx.y, b = blockIdx.z;
    const int kvh = h >> 2;
    const int q0  = qt * 64;

    const h16* Qg = qkv + ((size_t)(b*L_ + q0)) * QKVD_ + h * HD_;
    const h16* Kg = qkv + ((size_t)(b*L_)) * QKVD_ + 2048 + kvh * HD_;
    const h16* Vg = vt + ((size_t)(b*KVH_ + kvh)) * HD_ * L_;

    // ldmatrix lane-address components
    const int a_row = (lane & 7) + ((lane >> 3) & 1) * 8;
    const int a_c8  = ((lane >> 4) & 1) * 8;
    const int b_row = (lane & 7) + ((lane >> 4) & 1) * 8;
    const int b_c8  = ((lane >> 3) & 1) * 8;

    const uint32_t qsu = (uint32_t)__cvta_generic_to_shared(Qs);
    const uint32_t ksu = (uint32_t)__cvta_generic_to_shared(Ks);
    const uint32_t vsu = (uint32_t)__cvta_generic_to_shared(Vs);

    const uint32_t aBase = qsu + (uint32_t)((w*16 + a_row)*QPAD + a_c8) * 2u;
    const uint32_t kBase0 = ksu + (uint32_t)(b_row*QPAD + b_c8) * 2u;
    const uint32_t vBase0 = vsu + (uint32_t)(b_row*VPAD + b_c8) * 2u;

#pragma unroll
    for (int i = 0; i < 8; i++) {
        int c = tid + i * 128;
        int row = c >> 4, ch = c & 15;
        cp16(Qs + row*QPAD + ch*8, Qg + (size_t)row * QKVD_ + ch*8);
    }

    auto load_stage = [&](int s, int kt) {
        const int j0 = kt * 64;
#pragma unroll
        for (int i = 0; i < 8; i++) {
            int c = tid + i * 128;
            int row = c >> 4, ch = c & 15;
            cp16(Ks + s*KPL + row*QPAD + ch*8,
                 Kg + (size_t)(j0 + row) * QKVD_ + ch*8);
        }
#pragma unroll
        for (int i = 0; i < 8; i++) {
            int c = tid + i * 128;
            int row = c >> 3, ch = c & 7;
            cp16(Vs + s*VPL + row*VPAD + ch*8,
                 Vg + (size_t)row * L_ + j0 + ch*8);
        }
        if (tid < 64)
            Ms[s*64 + tid] = mask[b*L_ + j0 + tid] ? -6.0f : -1e30f;
    };

    load_stage(0, 0);
    cp_commit();

    float o[16][4];
#pragma unroll
    for (int i = 0; i < 16; i++)
#pragma unroll
        for (int c = 0; c < 4; c++) o[i][c] = 0.f;

    float lsum0 = 0.f, lsum1 = 0.f;
    const float sc = 0.08838834764831845f;

    const int NT_ = L_ / 64;
    for (int kt = 0; kt < NT_; kt++) {
        const int buf = kt & 1;
        if (kt + 1 < NT_) {
            load_stage(buf ^ 1, kt + 1);
            cp_commit();
            cp_wait<1>();
        } else {
            cp_wait<0>();
        }
        __syncthreads();

        // ---- S = Q K^T : per warp m16 x n64 x k128, ldmatrix ----
        float s[8][4];
#pragma unroll
        for (int nt = 0; nt < 8; nt++)
#pragma unroll
            for (int c = 0; c < 4; c++) s[nt][c] = 0.f;

        const uint32_t kBase = kBase0 + (uint32_t)(buf*KPL) * 2u;

#pragma unroll
        for (int kk = 0; kk < 8; kk++) {
            const int ko = kk * 16;
            uint32_t ah[4];
            ldsm4(ah, aBase + (uint32_t)ko * 2u);
#pragma unroll
            for (int nt2 = 0; nt2 < 4; nt2++) {
                uint32_t kb[4];
                ldsm4(kb, kBase + (uint32_t)(nt2*16*QPAD + ko) * 2u);
                mma_f16(s[2*nt2],   ah, kb);
                mma_f16(s[2*nt2+1], ah, kb + 2);
            }
        }

        // ---- fixed-shift exp + sum + fp16 P fragments ----
        const float* msf = Ms + buf*64;
        uint32_t pah[4][4];
#pragma unroll
        for (int kk = 0; kk < 4; kk++) {
            const int n0t = 2*kk, n1t = 2*kk + 1;
            float b00 = msf[8*n0t + 2*t], b01 = msf[8*n0t + 2*t + 1];
            float b10 = msf[8*n1t + 2*t], b11 = msf[8*n1t + 2*t + 1];
            float p00 = __expf(s[n0t][0]*sc + b00);
            float p01 = __expf(s[n0t][1]*sc + b01);
            float p02 = __expf(s[n0t][2]*sc + b00);
            float p03 = __expf(s[n0t][3]*sc + b01);
            float p10 = __expf(s[n1t][0]*sc + b10);
            float p11 = __expf(s[n1t][1]*sc + b11);
            float p12 = __expf(s[n1t][2]*sc + b10);
            float p13 = __expf(s[n1t][3]*sc + b11);
            lsum0 += p00 + p01 + p10 + p11;
            lsum1 += p02 + p03 + p12 + p13;
            pah[kk][0] = cvt2(p00, p01);
            pah[kk][1] = cvt2(p02, p03);
            pah[kk][2] = cvt2(p10, p11);
            pah[kk][3] = cvt2(p12, p13);
        }

        // ---- O += P V : per warp m16 x n128 x k64, ldmatrix ----
        const uint32_t vBase = vBase0 + (uint32_t)(buf*VPL) * 2u;
#pragma unroll
        for (int kk = 0; kk < 4; kk++) {
            const int ko = kk * 16;
#pragma unroll
            for (int nt2 = 0; nt2 < 8; nt2++) {
                uint32_t vb[4];
                ldsm4(vb, vBase + (uint32_t)(nt2*16*VPAD + ko) * 2u);
                mma_f16(o[2*nt2],   pah[kk], vb);
                mma_f16(o[2*nt2+1], pah[kk], vb + 2);
            }
        }
        __syncthreads();
    }

    lsum0 += __shfl_xor_sync(0xffffffffu, lsum0, 1);
    lsum0 += __shfl_xor_sync(0xffffffffu, lsum0, 2);
    lsum1 += __shfl_xor_sync(0xffffffffu, lsum1, 1);
    lsum1 += __shfl_xor_sync(0xffffffffu, lsum1, 2);

    const float inv0 = lsum0 > 0.f ? 1.f / lsum0 : 0.f;
    const float inv1 = lsum1 > 0.f ? 1.f / lsum1 : 0.f;
    const int g = lane >> 2;
    const int row0 = q0 + w*16 + g;
    const size_t base0 = (size_t)(b*L_ + row0) * D_ + h * HD_;
    const size_t base1 = base0 + 8 * (size_t)D_;

#pragma unroll
    for (int nt = 0; nt < 16; nt++) {
        const int col = nt*8 + 2*t;
        *(uint32_t*)(ao + base0 + col) = cvt2(o[nt][0] * inv0, o[nt][1] * inv0);
        *(uint32_t*)(ao + base1 + col) = cvt2(o[nt][2] * inv1, o[nt][3] * inv1);
    }
}

// ---------------------------------------------------------------------------
// Launch
// ---------------------------------------------------------------------------
extern "C" void kernel_launch(void* const* d_in, const int* in_sizes, int n_in,
                              void* d_out, int out_size) {
    const float* x    = (const float*)d_in[0];
    const int*   mask = (const int*)  d_in[1];
    const float* Wq   = (const float*)d_in[2];
    const float* Wk   = (const float*)d_in[3];
    const float* Wv   = (const float*)d_in[4];
    const float* Wo   = (const float*)d_in[5];
    const float* qg   = (const float*)d_in[6];
    const float* kg   = (const float*)d_in[7];
    float* out = (float*)d_out;

    h16 *x16, *wqkv, *wo16, *qkvp, *vtp, *aop;
    cudaGetSymbolAddress((void**)&x16,  g_x16);
    cudaGetSymbolAddress((void**)&wqkv, g_wqkv);
    cudaGetSymbolAddress((void**)&wo16, g_wo16);
    cudaGetSymbolAddress((void**)&qkvp, g_qkv);
    cudaGetSymbolAddress((void**)&vtp,  g_vt);
    cudaGetSymbolAddress((void**)&aop,  g_ao);

    cudaFuncSetAttribute(k_flash, cudaFuncAttributeMaxDynamicSharedMemorySize,
                         FA_SMEM_BYTES);

    static cudaStream_t s2 = nullptr;
    static cudaEvent_t e0 = nullptr, e2 = nullptr;
    if (!s2) {
        cudaStreamCreateWithFlags(&s2, cudaStreamNonBlocking);
        cudaEventCreateWithFlags(&e0, cudaEventDisableTiming);
        cudaEventCreateWithFlags(&e2, cudaEventDisableTiming);
    }

    const int M = B_ * L_;
    dim3 blk(256);

    // fork: Wo conversion concurrent until O-proj
    cudaEventRecord(e0, 0);
    cudaStreamWaitEvent(s2, e0, 0);
    k_cvt_wo<<<1048576u/256u, 256, 0, s2>>>((const float4*)Wo);
    cudaEventRecord(e2, s2);

    // x + packed Wq|Wk|Wv conversion
    k_cvt_main<<<CS3/256u, 256>>>((const float4*)x, (const float4*)Wq,
                                  (const float4*)Wk, (const float4*)Wv);

    // merged QKV projection (Q/K rms+rope fused; V written transposed)
    k_gemm<3><<<dim3(QKVD_/BN, M/BM), blk, SMEM_TB_BYTES>>>(
        x16, D_, wqkv, D_, qkvp, QKVD_, D_, qg, kg, vtp);

    // fused flash attention
    k_flash<<<dim3(L_/64, H_, B_), 128, FA_SMEM_BYTES>>>(qkvp, vtp, mask, aop);

    // join s2, output projection (fp32 out)
    cudaStreamWaitEvent(0, e2, 0);
    k_gemm<0><<<dim3(D_/BN, M/BM), blk, SMEM_TB_BYTES>>>(
        aop, D_, wo16, D_, out, D_, D_, nullptr, nullptr, nullptr);
}

// round 14
// speedup vs baseline: 1.0746x; 1.0252x over previous
#include <cuda_runtime.h>
#include <cuda_fp16.h>
#include <math.h>
#include <math_constants.h>
#include <stdint.h>

#define B_    2
#define L_    2048
#define D_    2048
#define H_    16
#define KVH_  4
#define HD_   128
#define QKVD_ 3072
#define EPS_  1e-6f

typedef __half h16;

// ---------------------------------------------------------------------------
// Static scratch (all fp16)
// ---------------------------------------------------------------------------
__device__ h16 g_x16 [B_*L_*D_];
__device__ h16 g_wqkv[QKVD_*D_];        // rows 0-2047 Wq, 2048-2559 Wk, 2560-3071 Wv
__device__ h16 g_wo16[D_*D_];
__device__ h16 g_qkv [B_*L_*QKVD_];
__device__ h16 g_vt  [B_*KVH_*HD_*L_];
__device__ h16 g_ao  [B_*L_*D_];

// ---------------------------------------------------------------------------
// PTX helpers
// ---------------------------------------------------------------------------
__device__ __forceinline__ void mma_f16(float* c, const uint32_t* a, const uint32_t* b) {
    asm volatile(
        "mma.sync.aligned.m16n8k16.row.col.f32.f16.f16.f32 "
        "{%0,%1,%2,%3}, {%4,%5,%6,%7}, {%8,%9}, {%0,%1,%2,%3};\n"
        : "+f"(c[0]), "+f"(c[1]), "+f"(c[2]), "+f"(c[3])
        : "r"(a[0]), "r"(a[1]), "r"(a[2]), "r"(a[3]), "r"(b[0]), "r"(b[1]));
}

__device__ __forceinline__ void ldsm4(uint32_t* r, uint32_t saddr) {
    asm volatile("ldmatrix.sync.aligned.m8n8.x4.shared.b16 {%0,%1,%2,%3}, [%4];"
        : "=r"(r[0]), "=r"(r[1]), "=r"(r[2]), "=r"(r[3]) : "r"(saddr));
}

__device__ __forceinline__ void cp16(const h16* dst_s, const h16* src_g) {
    uint32_t d = (uint32_t)__cvta_generic_to_shared(dst_s);
    asm volatile("cp.async.cg.shared.global [%0], [%1], 16;\n"
                 :: "r"(d), "l"(src_g) : "memory");
}
__device__ __forceinline__ void cp_commit() {
    asm volatile("cp.async.commit_group;\n" ::: "memory");
}
template<int N>
__device__ __forceinline__ void cp_wait() {
    asm volatile("cp.async.wait_group %0;\n" :: "n"(N) : "memory");
}

__device__ __forceinline__ uint32_t cvt2(float lo, float hi) {
    uint32_t r;
    asm("cvt.rn.f16x2.f32 %0, %1, %2;" : "=r"(r) : "f"(hi), "f"(lo));
    return r;
}

// ---------------------------------------------------------------------------
// GEMM (unchanged from round 13): ldmatrix fragment loads, fused epilogues.
// ---------------------------------------------------------------------------
#define BM 128
#define BN 128
#define BK 32
#define APAD 40

#define SM_A_HALVES (2*BM*APAD)
#define SM_B_HALVES (2*BN*APAD)
#define SMEM_TB_BYTES ((SM_A_HALVES + SM_B_HALVES)*2)   // 40960

#define INVF_C 0.2076205059304601f    // log2(10000)/64

template<int MODE>
__global__ __launch_bounds__(256, 2)
void k_gemm(const h16* __restrict__ A, int lda,
            const h16* __restrict__ Bh, int ldb,
            void* __restrict__ Cv, int ldc, int K,
            const float* __restrict__ qgamma,
            const float* __restrict__ kgamma,
            h16* __restrict__ vt)
{
    extern __shared__ h16 sh[];
    h16* sA = sh;
    h16* sB = sh + SM_A_HALVES;

    const int tid = threadIdx.x;
    const int m0 = blockIdx.y * BM;
    const int n0 = blockIdx.x * BN;

    const h16* Ap = A  + (size_t)m0 * lda;
    const h16* Bp = Bh + (size_t)n0 * ldb;

    const int lane = tid & 31;
    const int g    = lane >> 2;
    const int t    = lane & 3;
    const int warp = tid >> 5;
    const int wm   = warp >> 2;
    const int wn   = warp & 3;

    const int a_row = (lane & 7) + ((lane >> 3) & 1) * 8;
    const int a_c8  = ((lane >> 4) & 1) * 8;
    const int b_row = (lane & 7) + ((lane >> 4) & 1) * 8;
    const int b_c8  = ((lane >> 3) & 1) * 8;

    const uint32_t sAu = (uint32_t)__cvta_generic_to_shared(sA);
    const uint32_t sBu = (uint32_t)__cvta_generic_to_shared(sB);

    float acc[4][4][4];
#pragma unroll
    for (int i = 0; i < 4; i++)
#pragma unroll
        for (int j = 0; j < 4; j++)
#pragma unroll
            for (int c = 0; c < 4; c++) acc[i][j][c] = 0.f;

    auto load_stage = [&](int s, int k0) {
#pragma unroll
        for (int i = 0; i < 2; i++) {
            int c   = tid + i * 256;
            int row = c >> 2, kc = c & 3;
            cp16(sA + (size_t)s*BM*APAD + row*APAD + kc*8,
                 Ap + (size_t)row * lda + k0 + kc*8);
        }
#pragma unroll
        for (int i = 0; i < 2; i++) {
            int c   = tid + i * 256;
            int row = c >> 2, kc = c & 3;
            cp16(sB + (size_t)s*BN*APAD + row*APAD + kc*8,
                 Bp + (size_t)row * ldb + k0 + kc*8);
        }
    };

    const int nk = K / BK;
    load_stage(0, 0);
    cp_commit();

    for (int ks = 0; ks < nk; ks++) {
        const int buf = ks & 1;
        if (ks + 1 < nk) {
            load_stage(buf ^ 1, (ks + 1) * BK);
            cp_commit();
            cp_wait<1>();
        } else {
            cp_wait<0>();
        }
        __syncthreads();

        const uint32_t aBase = sAu + (uint32_t)(buf*BM*APAD + (wm*64 + a_row)*APAD + a_c8) * 2u;
        const uint32_t bBase = sBu + (uint32_t)(buf*BN*APAD + (wn*32 + b_row)*APAD + b_c8) * 2u;

#pragma unroll
        for (int kk = 0; kk < 2; kk++) {
            const int ko = kk * 16;

            uint32_t ah[4][4];
#pragma unroll
            for (int mt = 0; mt < 4; mt++)
                ldsm4(ah[mt], aBase + (uint32_t)(mt*16*APAD + ko) * 2u);

            uint32_t bb[2][4];
#pragma unroll
            for (int nt2 = 0; nt2 < 2; nt2++)
                ldsm4(bb[nt2], bBase + (uint32_t)(nt2*16*APAD + ko) * 2u);

#pragma unroll
            for (int mt = 0; mt < 4; mt++)
#pragma unroll
                for (int nt2 = 0; nt2 < 2; nt2++) {
                    mma_f16(acc[mt][2*nt2],   ah[mt], bb[nt2]);
                    mma_f16(acc[mt][2*nt2+1], ah[mt], bb[nt2] + 2);
                }
        }
        __syncthreads();
    }

    if constexpr (MODE == 0) {
        float* C = (float*)Cv;
#pragma unroll
        for (int mt = 0; mt < 4; mt++) {
            const int r = m0 + wm*64 + mt*16 + g;
#pragma unroll
            for (int nt = 0; nt < 4; nt++) {
                const int c = n0 + wn*32 + nt*8 + 2*t;
                *reinterpret_cast<float2*>(&C[(size_t)r     * ldc + c]) =
                    make_float2(acc[mt][nt][0], acc[mt][nt][1]);
                *reinterpret_cast<float2*>(&C[(size_t)(r+8) * ldc + c]) =
                    make_float2(acc[mt][nt][2], acc[mt][nt][3]);
            }
        }
    } else {
        h16* C = (h16*)Cv;
        if (n0 >= 2560) {
            const int kvh = (n0 - 2560) >> 7;
#pragma unroll
            for (int mt = 0; mt < 4; mt++)
#pragma unroll
                for (int hh = 0; hh < 2; hh++) {
                    const int r  = m0 + wm*64 + mt*16 + g + hh*8;
                    const int bb2 = r >> 11;
                    const int ll = r & (L_ - 1);
#pragma unroll
                    for (int nt = 0; nt < 4; nt++) {
                        const int d = wn*32 + nt*8 + 2*t;
                        size_t base = ((size_t)(bb2*KVH_ + kvh)*HD_ + d)*L_ + ll;
                        vt[base]      = __float2half_rn(acc[mt][nt][2*hh]);
                        vt[base + L_] = __float2half_rn(acc[mt][nt][2*hh+1]);
                    }
                }
        } else {
            const float* gamma = (n0 < 2048) ? qgamma : kgamma;
            float* red = (float*)sh;
            float part[4][2];
#pragma unroll
            for (int mt = 0; mt < 4; mt++)
#pragma unroll
                for (int hh = 0; hh < 2; hh++) {
                    float p = 0.f;
#pragma unroll
                    for (int nt = 0; nt < 4; nt++) {
                        float a0 = acc[mt][nt][2*hh], a1 = acc[mt][nt][2*hh+1];
                        p += a0*a0 + a1*a1;
                    }
                    p += __shfl_xor_sync(0xffffffffu, p, 1);
                    p += __shfl_xor_sync(0xffffffffu, p, 2);
                    part[mt][hh] = p;
                }
            if (t == 0) {
#pragma unroll
                for (int mt = 0; mt < 4; mt++)
#pragma unroll
                    for (int hh = 0; hh < 2; hh++)
                        red[(wm*64 + mt*16 + g + hh*8)*4 + wn] = part[mt][hh];
            }
            __syncthreads();

            float invv[4][2];
#pragma unroll
            for (int mt = 0; mt < 4; mt++)
#pragma unroll
                for (int hh = 0; hh < 2; hh++) {
                    int rl = wm*64 + mt*16 + g + hh*8;
                    float s = red[rl*4] + red[rl*4+1] + red[rl*4+2] + red[rl*4+3];
                    invv[mt][hh] = rsqrtf(s * (1.0f/HD_) + EPS_);
                }

            float invf[4], g0[4], g1[4];
#pragma unroll
            for (int nt = 0; nt < 4; nt++) {
                int p = wn*16 + nt*4 + t;
                invf[nt] = exp2f(-(float)p * INVF_C);
                g0[nt] = gamma[2*p];
                g1[nt] = gamma[2*p+1];
            }

#pragma unroll
            for (int mt = 0; mt < 4; mt++)
#pragma unroll
                for (int hh = 0; hh < 2; hh++) {
                    const int r  = m0 + wm*64 + mt*16 + g + hh*8;
                    const float fl = (float)(r & (L_-1));
                    const float iv = invv[mt][hh];
#pragma unroll
                    for (int nt = 0; nt < 4; nt++) {
                        float sn, cs;
                        sincosf(fl * invf[nt], &sn, &cs);
                        float re = acc[mt][nt][2*hh]   * iv * g0[nt];
                        float im = acc[mt][nt][2*hh+1] * iv * g1[nt];
                        h16* dst = C + (size_t)r * ldc + n0 + wn*32 + nt*8 + 2*t;
                        *(uint32_t*)dst = cvt2(re*cs - im*sn, re*sn + im*cs);
                    }
                }
        }
    }
}

// ---------------------------------------------------------------------------
// fp32->fp16 conversion
// ---------------------------------------------------------------------------
#define CS0 2097152u
#define CS1 (CS0 + 1048576u)
#define CS2 (CS1 + 262144u)
#define CS3 (CS2 + 262144u)

__device__ __forceinline__ ushort4 cvt4(float4 v) {
    uint32_t lo = 0, hi = 0;
    asm("cvt.rn.f16x2.f32 %0, %1, %2;" : "=r"(lo) : "f"(v.y), "f"(v.x));
    asm("cvt.rn.f16x2.f32 %0, %1, %2;" : "=r"(hi) : "f"(v.w), "f"(v.z));
    ushort4 r;
    r.x = (unsigned short)(lo & 0xffff);
    r.y = (unsigned short)(lo >> 16);
    r.z = (unsigned short)(hi & 0xffff);
    r.w = (unsigned short)(hi >> 16);
    return r;
}

__global__ void k_cvt_main(const float4* __restrict__ x, const float4* __restrict__ wq,
                           const float4* __restrict__ wk, const float4* __restrict__ wv)
{
    uint32_t i = blockIdx.x * 256u + threadIdx.x;
    ushort4* xh = (ushort4*)g_x16;
    ushort4* wh = (ushort4*)g_wqkv;
    if (i < CS0)      xh[i]                  = cvt4(x [i]);
    else if (i < CS1) wh[i - CS0]            = cvt4(wq[i - CS0]);
    else if (i < CS2) wh[i - CS1 + 1048576u] = cvt4(wk[i - CS1]);
    else if (i < CS3) wh[i - CS2 + 1310720u] = cvt4(wv[i - CS2]);
}

__global__ void k_cvt_wo(const float4* __restrict__ wo)
{
    uint32_t i = blockIdx.x * 256u + threadIdx.x;
    ((ushort4*)g_wo16)[i] = cvt4(wo[i]);
}

// ---------------------------------------------------------------------------
// Fused flash attention. K-tile 32, 128 threads, 3 CTAs/SM.
// Q fragments cached in registers (loaded once).
// ---------------------------------------------------------------------------
#define QPAD 136
#define VPAD2 40

#define QPL   (64*QPAD)           // 8704
#define KPL2  (32*QPAD)           // 4352
#define VPL2  (128*VPAD2)         // 5120
#define QS_OFF 0
#define KS_OFF QPL
#define VS_OFF (KS_OFF + 2*KPL2)  // 17408
#define MS_OFF_H (VS_OFF + 2*VPL2) // 27648
#define FA_SMEM_BYTES (MS_OFF_H*2 + 2*32*4)   // 55552

__global__ __launch_bounds__(128, 3)
void k_flash(const h16* __restrict__ qkv,
             const h16* __restrict__ vt,
             const int* __restrict__ mask,
             h16* __restrict__ ao)
{
    extern __shared__ h16 sm[];
    h16*   Qs = sm + QS_OFF;
    h16*   Ks = sm + KS_OFF;
    h16*   Vs = sm + VS_OFF;
    float* Ms = (float*)(sm + MS_OFF_H);

    const int tid  = threadIdx.x;
    const int lane = tid & 31;
    const int t    = lane & 3;
    const int w    = tid >> 5;

    const int qt = blockIdx.x, h = blockIdx.y, b = blockIdx.z;
    const int kvh = h >> 2;
    const int q0  = qt * 64;

    const h16* Qg = qkv + ((size_t)(b*L_ + q0)) * QKVD_ + h * HD_;
    const h16* Kg = qkv + ((size_t)(b*L_)) * QKVD_ + 2048 + kvh * HD_;
    const h16* Vg = vt + ((size_t)(b*KVH_ + kvh)) * HD_ * L_;

    const int a_row = (lane & 7) + ((lane >> 3) & 1) * 8;
    const int a_c8  = ((lane >> 4) & 1) * 8;
    const int b_row = (lane & 7) + ((lane >> 4) & 1) * 8;
    const int b_c8  = ((lane >> 3) & 1) * 8;

    const uint32_t qsu = (uint32_t)__cvta_generic_to_shared(Qs);
    const uint32_t ksu = (uint32_t)__cvta_generic_to_shared(Ks);
    const uint32_t vsu = (uint32_t)__cvta_generic_to_shared(Vs);

    const uint32_t aBase  = qsu + (uint32_t)((w*16 + a_row)*QPAD + a_c8) * 2u;
    const uint32_t kBase0 = ksu + (uint32_t)(b_row*QPAD + b_c8) * 2u;
    const uint32_t vBase0 = vsu + (uint32_t)(b_row*VPAD2 + b_c8) * 2u;

    // Q tile load (cp.async) : 64 rows x 16 chunks
#pragma unroll
    for (int i = 0; i < 8; i++) {
        int c = tid + i * 128;
        int row = c >> 4, ch = c & 15;
        cp16(Qs + row*QPAD + ch*8, Qg + (size_t)row * QKVD_ + ch*8);
    }

    auto load_stage = [&](int s, int kt) {
        const int j0 = kt * 32;
#pragma unroll
        for (int i = 0; i < 4; i++) {          // K: 32 rows x 16 chunks
            int c = tid + i * 128;
            int row = c >> 4, ch = c & 15;
            cp16(Ks + s*KPL2 + row*QPAD + ch*8,
                 Kg + (size_t)(j0 + row) * QKVD_ + ch*8);
        }
#pragma unroll
        for (int i = 0; i < 4; i++) {          // V: 128 d-rows x 4 chunks (32 l-cols)
            int c = tid + i * 128;
            int row = c >> 2, ch = c & 3;
            cp16(Vs + s*VPL2 + row*VPAD2 + ch*8,
                 Vg + (size_t)row * L_ + j0 + ch*8);
        }
        if (tid < 32)
            Ms[s*32 + tid] = mask[b*L_ + j0 + tid] ? -6.0f : -1e30f;
    };

    load_stage(0, 0);
    cp_commit();
    cp_wait<0>();
    __syncthreads();

    // cache Q fragments in registers (once)
    uint32_t qf[8][4];
#pragma unroll
    for (int kk = 0; kk < 8; kk++)
        ldsm4(qf[kk], aBase + (uint32_t)(kk * 16) * 2u);

    float o[16][4];
#pragma unroll
    for (int i = 0; i < 16; i++)
#pragma unroll
        for (int c = 0; c < 4; c++) o[i][c] = 0.f;

    float lsum0 = 0.f, lsum1 = 0.f;
    const float sc = 0.08838834764831845f;

    const int NT_ = L_ / 32;
    for (int kt = 0; kt < NT_; kt++) {
        const int buf = kt & 1;
        if (kt + 1 < NT_) {
            load_stage(buf ^ 1, kt + 1);
            cp_commit();
            cp_wait<1>();
        } else {
            cp_wait<0>();
        }
        __syncthreads();

        // ---- S = Q K^T : per warp m16 x n32 x k128 ----
        float s[4][4];
#pragma unroll
        for (int nt = 0; nt < 4; nt++)
#pragma unroll
            for (int c = 0; c < 4; c++) s[nt][c] = 0.f;

        const uint32_t kBase = kBase0 + (uint32_t)(buf*KPL2) * 2u;

#pragma unroll
        for (int kk = 0; kk < 8; kk++) {
            const int ko = kk * 16;
            uint32_t kb0[4], kb1[4];
            ldsm4(kb0, kBase + (uint32_t)ko * 2u);
            ldsm4(kb1, kBase + (uint32_t)(16*QPAD + ko) * 2u);
            mma_f16(s[0], qf[kk], kb0);
            mma_f16(s[1], qf[kk], kb0 + 2);
            mma_f16(s[2], qf[kk], kb1);
            mma_f16(s[3], qf[kk], kb1 + 2);
        }

        // ---- fixed-shift exp + sum + fp16 P fragments ----
        const float* msf = Ms + buf*32;
        uint32_t pah[2][4];
#pragma unroll
        for (int kk = 0; kk < 2; kk++) {
            const int n0t = 2*kk, n1t = 2*kk + 1;
            float b00 = msf[8*n0t + 2*t], b01 = msf[8*n0t + 2*t + 1];
            float b10 = msf[8*n1t + 2*t], b11 = msf[8*n1t + 2*t + 1];
            float p00 = __expf(s[n0t][0]*sc + b00);
            float p01 = __expf(s[n0t][1]*sc + b01);
            float p02 = __expf(s[n0t][2]*sc + b00);
            float p03 = __expf(s[n0t][3]*sc + b01);
            float p10 = __expf(s[n1t][0]*sc + b10);
            float p11 = __expf(s[n1t][1]*sc + b11);
            float p12 = __expf(s[n1t][2]*sc + b10);
            float p13 = __expf(s[n1t][3]*sc + b11);
            lsum0 += p00 + p01 + p10 + p11;
            lsum1 += p02 + p03 + p12 + p13;
            pah[kk][0] = cvt2(p00, p01);
            pah[kk][1] = cvt2(p02, p03);
            pah[kk][2] = cvt2(p10, p11);
            pah[kk][3] = cvt2(p12, p13);
        }

        // ---- O += P V : per warp m16 x n128 x k32 ----
        const uint32_t vBase = vBase0 + (uint32_t)(buf*VPL2) * 2u;
#pragma unroll
        for (int kk = 0; kk < 2; kk++) {
            const int ko = kk * 16;
#pragma unroll
            for (int nt2 = 0; nt2 < 8; nt2++) {
                uint32_t vb[4];
                ldsm4(vb, vBase + (uint32_t)(nt2*16*VPAD2 + ko) * 2u);
                mma_f16(o[2*nt2],   pah[kk], vb);
                mma_f16(o[2*nt2+1], pah[kk], vb + 2);
            }
        }
        __syncthreads();
    }

    lsum0 += __shfl_xor_sync(0xffffffffu, lsum0, 1);
    lsum0 += __shfl_xor_sync(0xffffffffu, lsum0, 2);
    lsum1 += __shfl_xor_sync(0xffffffffu, lsum1, 1);
    lsum1 += __shfl_xor_sync(0xffffffffu, lsum1, 2);

    const float inv0 = lsum0 > 0.f ? 1.f / lsum0 : 0.f;
    const float inv1 = lsum1 > 0.f ? 1.f / lsum1 : 0.f;
    const int g = lane >> 2;
    const int row0 = q0 + w*16 + g;
    const size_t base0 = (size_t)(b*L_ + row0) * D_ + h * HD_;
    const size_t base1 = base0 + 8 * (size_t)D_;

#pragma unroll
    for (int nt = 0; nt < 16; nt++) {
        const int col = nt*8 + 2*t;
        *(uint32_t*)(ao + base0 + col) = cvt2(o[nt][0] * inv0, o[nt][1] * inv0);
        *(uint32_t*)(ao + base1 + col) = cvt2(o[nt][2] * inv1, o[nt][3] * inv1);
    }
}

// ---------------------------------------------------------------------------
// Launch
// ---------------------------------------------------------------------------
extern "C" void kernel_launch(void* const* d_in, const int* in_sizes, int n_in,
                              void* d_out, int out_size) {
    const float* x    = (const float*)d_in[0];
    const int*   mask = (const int*)  d_in[1];
    const float* Wq   = (const float*)d_in[2];
    const float* Wk   = (const float*)d_in[3];
    const float* Wv   = (const float*)d_in[4];
    const float* Wo   = (const float*)d_in[5];
    const float* qg   = (const float*)d_in[6];
    const float* kg   = (const float*)d_in[7];
    float* out = (float*)d_out;

    h16 *x16, *wqkv, *wo16, *qkvp, *vtp, *aop;
    cudaGetSymbolAddress((void**)&x16,  g_x16);
    cudaGetSymbolAddress((void**)&wqkv, g_wqkv);
    cudaGetSymbolAddress((void**)&wo16, g_wo16);
    cudaGetSymbolAddress((void**)&qkvp, g_qkv);
    cudaGetSymbolAddress((void**)&vtp,  g_vt);
    cudaGetSymbolAddress((void**)&aop,  g_ao);

    cudaFuncSetAttribute(k_flash, cudaFuncAttributeMaxDynamicSharedMemorySize,
                         FA_SMEM_BYTES);

    static cudaStream_t s2 = nullptr;
    static cudaEvent_t e0 = nullptr, e2 = nullptr;
    if (!s2) {
        cudaStreamCreateWithFlags(&s2, cudaStreamNonBlocking);
        cudaEventCreateWithFlags(&e0, cudaEventDisableTiming);
        cudaEventCreateWithFlags(&e2, cudaEventDisableTiming);
    }

    const int M = B_ * L_;
    dim3 blk(256);

    cudaEventRecord(e0, 0);
    cudaStreamWaitEvent(s2, e0, 0);
    k_cvt_wo<<<1048576u/256u, 256, 0, s2>>>((const float4*)Wo);
    cudaEventRecord(e2, s2);

    k_cvt_main<<<CS3/256u, 256>>>((const float4*)x, (const float4*)Wq,
                                  (const float4*)Wk, (const float4*)Wv);

    k_gemm<3><<<dim3(QKVD_/BN, M/BM), blk, SMEM_TB_BYTES>>>(
        x16, D_, wqkv, D_, qkvp, QKVD_, D_, qg, kg, vtp);

    k_flash<<<dim3(L_/64, H_, B_), 128, FA_SMEM_BYTES>>>(qkvp, vtp, mask, aop);

    cudaStreamWaitEvent(0, e2, 0);
    k_gemm<0><<<dim3(D_/BN, M/BM), blk, SMEM_TB_BYTES>>>(
        aop, D_, wo16, D_, out, D_, D_, nullptr, nullptr, nullptr);
}

// round 15
// speedup vs baseline: 1.1740x; 1.0925x over previous
#include <cuda_runtime.h>
#include <cuda_fp16.h>
#include <math.h>
#include <math_constants.h>
#include <stdint.h>

#define B_    2
#define L_    2048
#define D_    2048
#define H_    16
#define KVH_  4
#define HD_   128
#define QKVD_ 3072
#define EPS_  1e-6f

typedef __half h16;

// ---------------------------------------------------------------------------
// Static scratch (all fp16)
// ---------------------------------------------------------------------------
__device__ h16 g_x16 [B_*L_*D_];
__device__ h16 g_wqkv[QKVD_*D_];        // rows 0-2047 Wq, 2048-2559 Wk, 2560-3071 Wv
__device__ h16 g_wo16[D_*D_];
__device__ h16 g_qkv [B_*L_*QKVD_];
__device__ h16 g_vt  [B_*KVH_*HD_*L_];
__device__ h16 g_ao  [B_*L_*D_];

// ---------------------------------------------------------------------------
// PTX helpers
// ---------------------------------------------------------------------------
__device__ __forceinline__ void mma_f16(float* c, const uint32_t* a, const uint32_t* b) {
    asm volatile(
        "mma.sync.aligned.m16n8k16.row.col.f32.f16.f16.f32 "
        "{%0,%1,%2,%3}, {%4,%5,%6,%7}, {%8,%9}, {%0,%1,%2,%3};\n"
        : "+f"(c[0]), "+f"(c[1]), "+f"(c[2]), "+f"(c[3])
        : "r"(a[0]), "r"(a[1]), "r"(a[2]), "r"(a[3]), "r"(b[0]), "r"(b[1]));
}

__device__ __forceinline__ void ldsm4(uint32_t* r, uint32_t saddr) {
    asm volatile("ldmatrix.sync.aligned.m8n8.x4.shared.b16 {%0,%1,%2,%3}, [%4];"
        : "=r"(r[0]), "=r"(r[1]), "=r"(r[2]), "=r"(r[3]) : "r"(saddr));
}

__device__ __forceinline__ void cp16(const h16* dst_s, const h16* src_g) {
    uint32_t d = (uint32_t)__cvta_generic_to_shared(dst_s);
    asm volatile("cp.async.cg.shared.global [%0], [%1], 16;\n"
                 :: "r"(d), "l"(src_g) : "memory");
}
__device__ __forceinline__ void cp_commit() {
    asm volatile("cp.async.commit_group;\n" ::: "memory");
}
template<int N>
__device__ __forceinline__ void cp_wait() {
    asm volatile("cp.async.wait_group %0;\n" :: "n"(N) : "memory");
}

__device__ __forceinline__ uint32_t cvt2(float lo, float hi) {
    uint32_t r;
    asm("cvt.rn.f16x2.f32 %0, %1, %2;" : "=r"(r) : "f"(hi), "f"(lo));
    return r;
}

// ---------------------------------------------------------------------------
// GEMM: BK=64 (half the barriers of BK=32), ldmatrix fragments, fused epilogues.
// MODE 0: fp32 out (O projection).
// MODE 3: merged QKV epilogue (Q/K rms+rope; V transposed store).
// ---------------------------------------------------------------------------
#define BM 128
#define BN 128
#define BK 64
#define APAD 72      // halves/row (144B stride, ldsm conflict-free)

#define SM_A_HALVES (2*BM*APAD)          // 18432
#define SM_B_HALVES (2*BN*APAD)          // 18432
#define SMEM_TB_BYTES ((SM_A_HALVES + SM_B_HALVES)*2)   // 73728

#define INVF_C 0.2076205059304601f    // log2(10000)/64

template<int MODE>
__global__ __launch_bounds__(256, 2)
void k_gemm(const h16* __restrict__ A, int lda,
            const h16* __restrict__ Bh, int ldb,
            void* __restrict__ Cv, int ldc, int K,
            const float* __restrict__ qgamma,
            const float* __restrict__ kgamma,
            h16* __restrict__ vt)
{
    extern __shared__ h16 sh[];
    h16* sA = sh;
    h16* sB = sh + SM_A_HALVES;

    const int tid = threadIdx.x;
    const int m0 = blockIdx.y * BM;
    const int n0 = blockIdx.x * BN;

    const h16* Ap = A  + (size_t)m0 * lda;
    const h16* Bp = Bh + (size_t)n0 * ldb;

    const int lane = tid & 31;
    const int g    = lane >> 2;
    const int t    = lane & 3;
    const int warp = tid >> 5;
    const int wm   = warp >> 2;
    const int wn   = warp & 3;

    const int a_row = (lane & 7) + ((lane >> 3) & 1) * 8;
    const int a_c8  = ((lane >> 4) & 1) * 8;
    const int b_row = (lane & 7) + ((lane >> 4) & 1) * 8;
    const int b_c8  = ((lane >> 3) & 1) * 8;

    const uint32_t sAu = (uint32_t)__cvta_generic_to_shared(sA);
    const uint32_t sBu = (uint32_t)__cvta_generic_to_shared(sB);

    float acc[4][4][4];
#pragma unroll
    for (int i = 0; i < 4; i++)
#pragma unroll
        for (int j = 0; j < 4; j++)
#pragma unroll
            for (int c = 0; c < 4; c++) acc[i][j][c] = 0.f;

    auto load_stage = [&](int s, int k0) {
        // A: 128 rows x 8 chunks(16B) = 1024 cp16 over 256 threads
#pragma unroll
        for (int i = 0; i < 4; i++) {
            int c   = tid + i * 256;
            int row = c >> 3, kc = c & 7;
            cp16(sA + (size_t)s*BM*APAD + row*APAD + kc*8,
                 Ap + (size_t)row * lda + k0 + kc*8);
        }
#pragma unroll
        for (int i = 0; i < 4; i++) {
            int c   = tid + i * 256;
            int row = c >> 3, kc = c & 7;
            cp16(sB + (size_t)s*BN*APAD + row*APAD + kc*8,
                 Bp + (size_t)row * ldb + k0 + kc*8);
        }
    };

    const int nk = K / BK;
    load_stage(0, 0);
    cp_commit();

    for (int ks = 0; ks < nk; ks++) {
        const int buf = ks & 1;
        if (ks + 1 < nk) {
            load_stage(buf ^ 1, (ks + 1) * BK);
            cp_commit();
            cp_wait<1>();
        } else {
            cp_wait<0>();
        }
        __syncthreads();

        const uint32_t aBase = sAu + (uint32_t)(buf*BM*APAD + (wm*64 + a_row)*APAD + a_c8) * 2u;
        const uint32_t bBase = sBu + (uint32_t)(buf*BN*APAD + (wn*32 + b_row)*APAD + b_c8) * 2u;

#pragma unroll
        for (int kk = 0; kk < 4; kk++) {
            const int ko = kk * 16;

            uint32_t ah[4][4];
#pragma unroll
            for (int mt = 0; mt < 4; mt++)
                ldsm4(ah[mt], aBase + (uint32_t)(mt*16*APAD + ko) * 2u);

            uint32_t bb[2][4];
#pragma unroll
            for (int nt2 = 0; nt2 < 2; nt2++)
                ldsm4(bb[nt2], bBase + (uint32_t)(nt2*16*APAD + ko) * 2u);

#pragma unroll
            for (int mt = 0; mt < 4; mt++)
#pragma unroll
                for (int nt2 = 0; nt2 < 2; nt2++) {
                    mma_f16(acc[mt][2*nt2],   ah[mt], bb[nt2]);
                    mma_f16(acc[mt][2*nt2+1], ah[mt], bb[nt2] + 2);
                }
        }
        __syncthreads();
    }

    // ---------------- epilogue ----------------
    if constexpr (MODE == 0) {
        float* C = (float*)Cv;
#pragma unroll
        for (int mt = 0; mt < 4; mt++) {
            const int r = m0 + wm*64 + mt*16 + g;
#pragma unroll
            for (int nt = 0; nt < 4; nt++) {
                const int c = n0 + wn*32 + nt*8 + 2*t;
                *reinterpret_cast<float2*>(&C[(size_t)r     * ldc + c]) =
                    make_float2(acc[mt][nt][0], acc[mt][nt][1]);
                *reinterpret_cast<float2*>(&C[(size_t)(r+8) * ldc + c]) =
                    make_float2(acc[mt][nt][2], acc[mt][nt][3]);
            }
        }
    } else {
        h16* C = (h16*)Cv;
        if (n0 >= 2560) {
            const int kvh = (n0 - 2560) >> 7;
#pragma unroll
            for (int mt = 0; mt < 4; mt++)
#pragma unroll
                for (int hh = 0; hh < 2; hh++) {
                    const int r  = m0 + wm*64 + mt*16 + g + hh*8;
                    const int bb2 = r >> 11;
                    const int ll = r & (L_ - 1);
#pragma unroll
                    for (int nt = 0; nt < 4; nt++) {
                        const int d = wn*32 + nt*8 + 2*t;
                        size_t base = ((size_t)(bb2*KVH_ + kvh)*HD_ + d)*L_ + ll;
                        vt[base]      = __float2half_rn(acc[mt][nt][2*hh]);
                        vt[base + L_] = __float2half_rn(acc[mt][nt][2*hh+1]);
                    }
                }
        } else {
            const float* gamma = (n0 < 2048) ? qgamma : kgamma;
            float* red = (float*)sh;
            float part[4][2];
#pragma unroll
            for (int mt = 0; mt < 4; mt++)
#pragma unroll
                for (int hh = 0; hh < 2; hh++) {
                    float p = 0.f;
#pragma unroll
                    for (int nt = 0; nt < 4; nt++) {
                        float a0 = acc[mt][nt][2*hh], a1 = acc[mt][nt][2*hh+1];
                        p += a0*a0 + a1*a1;
                    }
                    p += __shfl_xor_sync(0xffffffffu, p, 1);
                    p += __shfl_xor_sync(0xffffffffu, p, 2);
                    part[mt][hh] = p;
                }
            if (t == 0) {
#pragma unroll
                for (int mt = 0; mt < 4; mt++)
#pragma unroll
                    for (int hh = 0; hh < 2; hh++)
                        red[(wm*64 + mt*16 + g + hh*8)*4 + wn] = part[mt][hh];
            }
            __syncthreads();

            float invv[4][2];
#pragma unroll
            for (int mt = 0; mt < 4; mt++)
#pragma unroll
                for (int hh = 0; hh < 2; hh++) {
                    int rl = wm*64 + mt*16 + g + hh*8;
                    float s = red[rl*4] + red[rl*4+1] + red[rl*4+2] + red[rl*4+3];
                    invv[mt][hh] = rsqrtf(s * (1.0f/HD_) + EPS_);
                }

            float invf[4], g0[4], g1[4];
#pragma unroll
            for (int nt = 0; nt < 4; nt++) {
                int p = wn*16 + nt*4 + t;
                invf[nt] = exp2f(-(float)p * INVF_C);
                g0[nt] = gamma[2*p];
                g1[nt] = gamma[2*p+1];
            }

#pragma unroll
            for (int mt = 0; mt < 4; mt++)
#pragma unroll
                for (int hh = 0; hh < 2; hh++) {
                    const int r  = m0 + wm*64 + mt*16 + g + hh*8;
                    const float fl = (float)(r & (L_-1));
                    const float iv = invv[mt][hh];
#pragma unroll
                    for (int nt = 0; nt < 4; nt++) {
                        float sn, cs;
                        sincosf(fl * invf[nt], &sn, &cs);
                        float re = acc[mt][nt][2*hh]   * iv * g0[nt];
                        float im = acc[mt][nt][2*hh+1] * iv * g1[nt];
                        h16* dst = C + (size_t)r * ldc + n0 + wn*32 + nt*8 + 2*t;
                        *(uint32_t*)dst = cvt2(re*cs - im*sn, re*sn + im*cs);
                    }
                }
        }
    }
}

// ---------------------------------------------------------------------------
// fp32->fp16 conversion
// ---------------------------------------------------------------------------
#define CS0 2097152u
#define CS1 (CS0 + 1048576u)
#define CS2 (CS1 + 262144u)
#define CS3 (CS2 + 262144u)

__device__ __forceinline__ ushort4 cvt4(float4 v) {
    uint32_t lo = 0, hi = 0;
    asm("cvt.rn.f16x2.f32 %0, %1, %2;" : "=r"(lo) : "f"(v.y), "f"(v.x));
    asm("cvt.rn.f16x2.f32 %0, %1, %2;" : "=r"(hi) : "f"(v.w), "f"(v.z));
    ushort4 r;
    r.x = (unsigned short)(lo & 0xffff);
    r.y = (unsigned short)(lo >> 16);
    r.z = (unsigned short)(hi & 0xffff);
    r.w = (unsigned short)(hi >> 16);
    return r;
}

__global__ void k_cvt_main(const float4* __restrict__ x, const float4* __restrict__ wq,
                           const float4* __restrict__ wk, const float4* __restrict__ wv)
{
    uint32_t i = blockIdx.x * 256u + threadIdx.x;
    ushort4* xh = (ushort4*)g_x16;
    ushort4* wh = (ushort4*)g_wqkv;
    if (i < CS0)      xh[i]                  = cvt4(x [i]);
    else if (i < CS1) wh[i - CS0]            = cvt4(wq[i - CS0]);
    else if (i < CS2) wh[i - CS1 + 1048576u] = cvt4(wk[i - CS1]);
    else if (i < CS3) wh[i - CS2 + 1310720u] = cvt4(wv[i - CS2]);
}

__global__ void k_cvt_wo(const float4* __restrict__ wo)
{
    uint32_t i = blockIdx.x * 256u + threadIdx.x;
    ((ushort4*)g_wo16)[i] = cvt4(wo[i]);
}

// ---------------------------------------------------------------------------
// Fused flash attention (unchanged from round 14).
// K-tile 32, 128 threads, 3 CTAs/SM, Q fragments cached in registers.
// ---------------------------------------------------------------------------
#define QPAD 136
#define VPAD2 40

#define QPL   (64*QPAD)
#define KPL2  (32*QPAD)
#define VPL2  (128*VPAD2)
#define QS_OFF 0
#define KS_OFF QPL
#define VS_OFF (KS_OFF + 2*KPL2)
#define MS_OFF_H (VS_OFF + 2*VPL2)
#define FA_SMEM_BYTES (MS_OFF_H*2 + 2*32*4)   // 55552

__global__ __launch_bounds__(128, 3)
void k_flash(const h16* __restrict__ qkv,
             const h16* __restrict__ vt,
             const int* __restrict__ mask,
             h16* __restrict__ ao)
{
    extern __shared__ h16 sm[];
    h16*   Qs = sm + QS_OFF;
    h16*   Ks = sm + KS_OFF;
    h16*   Vs = sm + VS_OFF;
    float* Ms = (float*)(sm + MS_OFF_H);

    const int tid  = threadIdx.x;
    const int lane = tid & 31;
    const int t    = lane & 3;
    const int w    = tid >> 5;

    const int qt = blockIdx.x, h = blockIdx.y, b = blockIdx.z;
    const int kvh = h >> 2;
    const int q0  = qt * 64;

    const h16* Qg = qkv + ((size_t)(b*L_ + q0)) * QKVD_ + h * HD_;
    const h16* Kg = qkv + ((size_t)(b*L_)) * QKVD_ + 2048 + kvh * HD_;
    const h16* Vg = vt + ((size_t)(b*KVH_ + kvh)) * HD_ * L_;

    const int a_row = (lane & 7) + ((lane >> 3) & 1) * 8;
    const int a_c8  = ((lane >> 4) & 1) * 8;
    const int b_row = (lane & 7) + ((lane >> 4) & 1) * 8;
    const int b_c8  = ((lane >> 3) & 1) * 8;

    const uint32_t qsu = (uint32_t)__cvta_generic_to_shared(Qs);
    const uint32_t ksu = (uint32_t)__cvta_generic_to_shared(Ks);
    const uint32_t vsu = (uint32_t)__cvta_generic_to_shared(Vs);

    const uint32_t aBase  = qsu + (uint32_t)((w*16 + a_row)*QPAD + a_c8) * 2u;
    const uint32_t kBase0 = ksu + (uint32_t)(b_row*QPAD + b_c8) * 2u;
    const uint32_t vBase0 = vsu + (uint32_t)(b_row*VPAD2 + b_c8) * 2u;

#pragma unroll
    for (int i = 0; i < 8; i++) {
        int c = tid + i * 128;
        int row = c >> 4, ch = c & 15;
        cp16(Qs + row*QPAD + ch*8, Qg + (size_t)row * QKVD_ + ch*8);
    }

    auto load_stage = [&](int s, int kt) {
        const int j0 = kt * 32;
#pragma unroll
        for (int i = 0; i < 4; i++) {
            int c = tid + i * 128;
            int row = c >> 4, ch = c & 15;
            cp16(Ks + s*KPL2 + row*QPAD + ch*8,
                 Kg + (size_t)(j0 + row) * QKVD_ + ch*8);
        }
#pragma unroll
        for (int i = 0; i < 4; i++) {
            int c = tid + i * 128;
            int row = c >> 2, ch = c & 3;
            cp16(Vs + s*VPL2 + row*VPAD2 + ch*8,
                 Vg + (size_t)row * L_ + j0 + ch*8);
        }
        if (tid < 32)
            Ms[s*32 + tid] = mask[b*L_ + j0 + tid] ? -6.0f : -1e30f;
    };

    load_stage(0, 0);
    cp_commit();
    cp_wait<0>();
    __syncthreads();

    uint32_t qf[8][4];
#pragma unroll
    for (int kk = 0; kk < 8; kk++)
        ldsm4(qf[kk], aBase + (uint32_t)(kk * 16) * 2u);

    float o[16][4];
#pragma unroll
    for (int i = 0; i < 16; i++)
#pragma unroll
        for (int c = 0; c < 4; c++) o[i][c] = 0.f;

    float lsum0 = 0.f, lsum1 = 0.f;
    const float sc = 0.08838834764831845f;

    const int NT_ = L_ / 32;
    for (int kt = 0; kt < NT_; kt++) {
        const int buf = kt & 1;
        if (kt + 1 < NT_) {
            load_stage(buf ^ 1, kt + 1);
            cp_commit();
            cp_wait<1>();
        } else {
            cp_wait<0>();
        }
        __syncthreads();

        float s[4][4];
#pragma unroll
        for (int nt = 0; nt < 4; nt++)
#pragma unroll
            for (int c = 0; c < 4; c++) s[nt][c] = 0.f;

        const uint32_t kBase = kBase0 + (uint32_t)(buf*KPL2) * 2u;

#pragma unroll
        for (int kk = 0; kk < 8; kk++) {
            const int ko = kk * 16;
            uint32_t kb0[4], kb1[4];
            ldsm4(kb0, kBase + (uint32_t)ko * 2u);
            ldsm4(kb1, kBase + (uint32_t)(16*QPAD + ko) * 2u);
            mma_f16(s[0], qf[kk], kb0);
            mma_f16(s[1], qf[kk], kb0 + 2);
            mma_f16(s[2], qf[kk], kb1);
            mma_f16(s[3], qf[kk], kb1 + 2);
        }

        const float* msf = Ms + buf*32;
        uint32_t pah[2][4];
#pragma unroll
        for (int kk = 0; kk < 2; kk++) {
            const int n0t = 2*kk, n1t = 2*kk + 1;
            float b00 = msf[8*n0t + 2*t], b01 = msf[8*n0t + 2*t + 1];
            float b10 = msf[8*n1t + 2*t], b11 = msf[8*n1t + 2*t + 1];
            float p00 = __expf(s[n0t][0]*sc + b00);
            float p01 = __expf(s[n0t][1]*sc + b01);
            float p02 = __expf(s[n0t][2]*sc + b00);
            float p03 = __expf(s[n0t][3]*sc + b01);
            float p10 = __expf(s[n1t][0]*sc + b10);
            float p11 = __expf(s[n1t][1]*sc + b11);
            float p12 = __expf(s[n1t][2]*sc + b10);
            float p13 = __expf(s[n1t][3]*sc + b11);
            lsum0 += p00 + p01 + p10 + p11;
            lsum1 += p02 + p03 + p12 + p13;
            pah[kk][0] = cvt2(p00, p01);
            pah[kk][1] = cvt2(p02, p03);
            pah[kk][2] = cvt2(p10, p11);
            pah[kk][3] = cvt2(p12, p13);
        }

        const uint32_t vBase = vBase0 + (uint32_t)(buf*VPL2) * 2u;
#pragma unroll
        for (int kk = 0; kk < 2; kk++) {
            const int ko = kk * 16;
#pragma unroll
            for (int nt2 = 0; nt2 < 8; nt2++) {
                uint32_t vb[4];
                ldsm4(vb, vBase + (uint32_t)(nt2*16*VPAD2 + ko) * 2u);
                mma_f16(o[2*nt2],   pah[kk], vb);
                mma_f16(o[2*nt2+1], pah[kk], vb + 2);
            }
        }
        __syncthreads();
    }

    lsum0 += __shfl_xor_sync(0xffffffffu, lsum0, 1);
    lsum0 += __shfl_xor_sync(0xffffffffu, lsum0, 2);
    lsum1 += __shfl_xor_sync(0xffffffffu, lsum1, 1);
    lsum1 += __shfl_xor_sync(0xffffffffu, lsum1, 2);

    const float inv0 = lsum0 > 0.f ? 1.f / lsum0 : 0.f;
    const float inv1 = lsum1 > 0.f ? 1.f / lsum1 : 0.f;
    const int g = lane >> 2;
    const int row0 = q0 + w*16 + g;
    const size_t base0 = (size_t)(b*L_ + row0) * D_ + h * HD_;
    const size_t base1 = base0 + 8 * (size_t)D_;

#pragma unroll
    for (int nt = 0; nt < 16; nt++) {
        const int col = nt*8 + 2*t;
        *(uint32_t*)(ao + base0 + col) = cvt2(o[nt][0] * inv0, o[nt][1] * inv0);
        *(uint32_t*)(ao + base1 + col) = cvt2(o[nt][2] * inv1, o[nt][3] * inv1);
    }
}

// ---------------------------------------------------------------------------
// Launch
// ---------------------------------------------------------------------------
extern "C" void kernel_launch(void* const* d_in, const int* in_sizes, int n_in,
                              void* d_out, int out_size) {
    const float* x    = (const float*)d_in[0];
    const int*   mask = (const int*)  d_in[1];
    const float* Wq   = (const float*)d_in[2];
    const float* Wk   = (const float*)d_in[3];
    const float* Wv   = (const float*)d_in[4];
    const float* Wo   = (const float*)d_in[5];
    const float* qg   = (const float*)d_in[6];
    const float* kg   = (const float*)d_in[7];
    float* out = (float*)d_out;

    h16 *x16, *wqkv, *wo16, *qkvp, *vtp, *aop;
    cudaGetSymbolAddress((void**)&x16,  g_x16);
    cudaGetSymbolAddress((void**)&wqkv, g_wqkv);
    cudaGetSymbolAddress((void**)&wo16, g_wo16);
    cudaGetSymbolAddress((void**)&qkvp, g_qkv);
    cudaGetSymbolAddress((void**)&vtp,  g_vt);
    cudaGetSymbolAddress((void**)&aop,  g_ao);

    cudaFuncSetAttribute(k_flash, cudaFuncAttributeMaxDynamicSharedMemorySize,
                         FA_SMEM_BYTES);
    cudaFuncSetAttribute(k_gemm<0>, cudaFuncAttributeMaxDynamicSharedMemorySize,
                         SMEM_TB_BYTES);
    cudaFuncSetAttribute(k_gemm<3>, cudaFuncAttributeMaxDynamicSharedMemorySize,
                         SMEM_TB_BYTES);

    static cudaStream_t s2 = nullptr;
    static cudaEvent_t e0 = nullptr, e2 = nullptr;
    if (!s2) {
        cudaStreamCreateWithFlags(&s2, cudaStreamNonBlocking);
        cudaEventCreateWithFlags(&e0, cudaEventDisableTiming);
        cudaEventCreateWithFlags(&e2, cudaEventDisableTiming);
    }

    const int M = B_ * L_;
    dim3 blk(256);

    cudaEventRecord(e0, 0);
    cudaStreamWaitEvent(s2, e0, 0);
    k_cvt_wo<<<1048576u/256u, 256, 0, s2>>>((const float4*)Wo);
    cudaEventRecord(e2, s2);

    k_cvt_main<<<CS3/256u, 256>>>((const float4*)x, (const float4*)Wq,
                                  (const float4*)Wk, (const float4*)Wv);

    k_gemm<3><<<dim3(QKVD_/BN, M/BM), blk, SMEM_TB_BYTES>>>(
        x16, D_, wqkv, D_, qkvp, QKVD_, D_, qg, kg, vtp);

    k_flash<<<dim3(L_/64, H_, B_), 128, FA_SMEM_BYTES>>>(qkvp, vtp, mask, aop);

    cudaStreamWaitEvent(0, e2, 0);
    k_gemm<0><<<dim3(D_/BN, M/BM), blk, SMEM_TB_BYTES>>>(
        aop, D_, wo16, D_, out, D_, D_, nullptr, nullptr, nullptr);
}